// round 2
// baseline (speedup 1.0000x reference)
#include <cuda_runtime.h>
#include <cuda_bf16.h>
#include <math.h>

// Problem constants
#define B_   2
#define S_   2048
#define E_   2048
#define H_   16
#define KVH_ 4
#define D_   128
#define M_   (B_ * S_)        // 4096 rows
#define KVN_ (2 * KVH_ * D_)  // 1024

// ---------------- scratch (device globals; no allocs allowed) ----------------
__device__ float g_qproj[(size_t)M_ * E_];    // [B*S, H*D]  (=[B,S,H,D])
__device__ float g_kvproj[(size_t)M_ * KVN_]; // [B*S, 2*KVH*D]
__device__ float g_attno[(size_t)M_ * E_];    // [B*S, H*D]

// ======================= SGEMM: C = A @ W^T (+bias) ==========================
// A: [M,K] row-major, W: [N,K] row-major, C: [M,N]. M,N mult of 128, K mult of 16.
__global__ void __launch_bounds__(256) sgemm_nt(const float* __restrict__ A,
                                                const float* __restrict__ W,
                                                const float* __restrict__ bias,
                                                float* __restrict__ C,
                                                int M, int N, int K) {
    __shared__ float As[16][128];
    __shared__ float Bs[16][128];
    const int tid = threadIdx.x;
    const int tx = tid & 15;   // n sub-tile
    const int ty = tid >> 4;   // m sub-tile
    const int m0 = blockIdx.y * 128;
    const int n0 = blockIdx.x * 128;
    const int lr = tid >> 2;          // 0..63
    const int lc = (tid & 3) << 2;    // 0,4,8,12

    float acc[8][8];
#pragma unroll
    for (int i = 0; i < 8; i++)
#pragma unroll
        for (int j = 0; j < 8; j++) acc[i][j] = 0.f;

    for (int k0 = 0; k0 < K; k0 += 16) {
#pragma unroll
        for (int r = 0; r < 2; r++) {
            int row = lr + 64 * r;
            float4 av = *(const float4*)&A[(size_t)(m0 + row) * K + k0 + lc];
            As[lc + 0][row] = av.x; As[lc + 1][row] = av.y;
            As[lc + 2][row] = av.z; As[lc + 3][row] = av.w;
            float4 bv = *(const float4*)&W[(size_t)(n0 + row) * K + k0 + lc];
            Bs[lc + 0][row] = bv.x; Bs[lc + 1][row] = bv.y;
            Bs[lc + 2][row] = bv.z; Bs[lc + 3][row] = bv.w;
        }
        __syncthreads();
#pragma unroll
        for (int kk = 0; kk < 16; kk++) {
            float a[8], b[8];
            float4 t;
            t = *(float4*)&As[kk][ty * 8];     a[0]=t.x; a[1]=t.y; a[2]=t.z; a[3]=t.w;
            t = *(float4*)&As[kk][ty * 8 + 4]; a[4]=t.x; a[5]=t.y; a[6]=t.z; a[7]=t.w;
            t = *(float4*)&Bs[kk][tx * 8];     b[0]=t.x; b[1]=t.y; b[2]=t.z; b[3]=t.w;
            t = *(float4*)&Bs[kk][tx * 8 + 4]; b[4]=t.x; b[5]=t.y; b[6]=t.z; b[7]=t.w;
#pragma unroll
            for (int i = 0; i < 8; i++)
#pragma unroll
                for (int j = 0; j < 8; j++) acc[i][j] += a[i] * b[j];
        }
        __syncthreads();
    }
#pragma unroll
    for (int i = 0; i < 8; i++) {
        int m = m0 + ty * 8 + i;
#pragma unroll
        for (int j = 0; j < 8; j += 4) {
            int n = n0 + tx * 8 + j;
            float4 v;
            float b0 = bias ? bias[n + 0] : 0.f;
            float b1 = bias ? bias[n + 1] : 0.f;
            float b2 = bias ? bias[n + 2] : 0.f;
            float b3 = bias ? bias[n + 3] : 0.f;
            v.x = acc[i][j + 0] + b0;
            v.y = acc[i][j + 1] + b1;
            v.z = acc[i][j + 2] + b2;
            v.w = acc[i][j + 3] + b3;
            *(float4*)&C[(size_t)m * N + n] = v;
        }
    }
}

// ================================ RoPE (in place) ============================
// t: [M_, rowStride]; head h occupies cols h*128..h*128+127. s = m % S_.
__global__ void rope_kernel(float* __restrict__ t, int nHeads, int rowStride) {
    int idx = blockIdx.x * blockDim.x + threadIdx.x;
    int total = M_ * nHeads * 64;
    if (idx >= total) return;
    int i = idx & 63;
    int h = (idx >> 6) % nHeads;
    int m = idx / (64 * nHeads);
    int s = m & (S_ - 1);
    float inv = powf(10000.0f, -(float)i * (1.0f / 64.0f));
    float fr = (float)s * inv;
    float sn, cs;
    sincosf(fr, &sn, &cs);
    float* p = t + (size_t)m * rowStride + h * 128 + i;
    float v1 = p[0], v2 = p[64];
    p[0]  = v1 * cs - v2 * sn;
    p[64] = v2 * cs + v1 * sn;
}

// ============================ Flash attention ================================
// 256 threads = 8 warps; each warp owns 4 q rows; BK=64 K/V tile.
// Q: [B*S, H*D] (RoPE'd), KV: [B*S, 2*KVH*D] (K RoPE'd), O: [B*S, H*D].
#define BKf 64
#define KT_STRIDE 65
// smem floats: q 32*128, Kt 128*65, Vs 64*128, p 8*4*64
#define FLASH_SMEM_FLOATS (32 * 128 + 128 * KT_STRIDE + 64 * 128 + 8 * 4 * 64)

extern __shared__ float fsm[];
__global__ void __launch_bounds__(256) flash_kernel(const float* __restrict__ Q,
                                                    const float* __restrict__ KV,
                                                    float* __restrict__ O) {
    float* q_s = fsm;                        // [32][128]
    float* Kt  = q_s + 32 * 128;             // [128][65] transposed K
    float* Vs  = Kt + 128 * KT_STRIDE;       // [64][128]
    float* p_s = Vs + 64 * 128;              // [8*4][64]

    const int tid = threadIdx.x;
    const int warp = tid >> 5, lane = tid & 31;
    const int bh = blockIdx.y;               // 0..31
    const int b = bh >> 4, h = bh & 15;
    const int kvh = h >> 2;
    const int q0 = blockIdx.x * 32;
    const float scale = 0.08838834764831845f;  // 1/sqrt(128)

    // load 32 q rows
    for (int i = tid; i < 32 * (D_ / 4); i += 256) {
        int r = i >> 5;              // row 0..31
        int c = (i & 31) << 2;       // col 0..124
        *(float4*)&q_s[r * D_ + c] =
            *(const float4*)&Q[(size_t)(b * S_ + q0 + r) * E_ + h * 128 + c];
    }

    float m_r[4], l_r[4], o_acc[4][4];
#pragma unroll
    for (int r = 0; r < 4; r++) {
        m_r[r] = -1e30f; l_r[r] = 0.f;
#pragma unroll
        for (int i = 0; i < 4; i++) o_acc[r][i] = 0.f;
    }

    const float* Kbase = KV + (size_t)b * S_ * KVN_ + kvh * 128;
    const float* Vbase = KV + (size_t)b * S_ * KVN_ + KVH_ * 128 + kvh * 128;

    for (int kt = 0; kt < S_; kt += BKf) {
        __syncthreads();
        // load K (transposed) + V tiles: 64 rows x 128
#pragma unroll
        for (int it = 0; it < 8; it++) {
            int li = tid + it * 256;     // 0..2047
            int j = li >> 5;             // k row 0..63
            int d = (li & 31) << 2;
            float4 k4 = *(const float4*)&Kbase[(size_t)(kt + j) * KVN_ + d];
            Kt[(d + 0) * KT_STRIDE + j] = k4.x;
            Kt[(d + 1) * KT_STRIDE + j] = k4.y;
            Kt[(d + 2) * KT_STRIDE + j] = k4.z;
            Kt[(d + 3) * KT_STRIDE + j] = k4.w;
            float4 v4 = *(const float4*)&Vbase[(size_t)(kt + j) * KVN_ + d];
            *(float4*)&Vs[j * D_ + d] = v4;
        }
        __syncthreads();

        // phase 1: scores for columns (lane, lane+32) x 4 rows
        float s[4][2];
#pragma unroll
        for (int r = 0; r < 4; r++) { s[r][0] = 0.f; s[r][1] = 0.f; }
#pragma unroll
        for (int d4 = 0; d4 < D_; d4 += 4) {
            float k0[4], k1[4];
#pragma unroll
            for (int i = 0; i < 4; i++) {
                k0[i] = Kt[(d4 + i) * KT_STRIDE + lane];
                k1[i] = Kt[(d4 + i) * KT_STRIDE + lane + 32];
            }
#pragma unroll
            for (int r = 0; r < 4; r++) {
                float4 qv = *(float4*)&q_s[(warp * 4 + r) * D_ + d4];
                s[r][0] += qv.x * k0[0] + qv.y * k0[1] + qv.z * k0[2] + qv.w * k0[3];
                s[r][1] += qv.x * k1[0] + qv.y * k1[1] + qv.z * k1[2] + qv.w * k1[3];
            }
        }
        // online softmax per row
#pragma unroll
        for (int r = 0; r < 4; r++) {
            float s0 = s[r][0] * scale, s1 = s[r][1] * scale;
            float mx = fmaxf(s0, s1);
#pragma unroll
            for (int off = 16; off; off >>= 1)
                mx = fmaxf(mx, __shfl_xor_sync(0xffffffffu, mx, off));
            float mnew = fmaxf(m_r[r], mx);
            float p0 = expf(s0 - mnew), p1 = expf(s1 - mnew);
            float corr = expf(m_r[r] - mnew);
            float ps = p0 + p1;
#pragma unroll
            for (int off = 16; off; off >>= 1)
                ps += __shfl_xor_sync(0xffffffffu, ps, off);
            l_r[r] = l_r[r] * corr + ps;
            m_r[r] = mnew;
#pragma unroll
            for (int i = 0; i < 4; i++) o_acc[r][i] *= corr;
            p_s[(warp * 4 + r) * 64 + lane] = p0;
            p_s[(warp * 4 + r) * 64 + lane + 32] = p1;
        }
        __syncwarp();
        // phase 2: O += P @ V  (lane owns d = lane*4..lane*4+3)
#pragma unroll 4
        for (int j = 0; j < BKf; j++) {
            float4 vv = *(float4*)&Vs[j * D_ + lane * 4];
#pragma unroll
            for (int r = 0; r < 4; r++) {
                float pj = p_s[(warp * 4 + r) * 64 + j];
                o_acc[r][0] += pj * vv.x;
                o_acc[r][1] += pj * vv.y;
                o_acc[r][2] += pj * vv.z;
                o_acc[r][3] += pj * vv.w;
            }
        }
    }
    // epilogue
#pragma unroll
    for (int r = 0; r < 4; r++) {
        float inv = 1.f / l_r[r];
        float4 ov;
        ov.x = o_acc[r][0] * inv; ov.y = o_acc[r][1] * inv;
        ov.z = o_acc[r][2] * inv; ov.w = o_acc[r][3] * inv;
        int srow = q0 + warp * 4 + r;
        *(float4*)&O[(size_t)(b * S_ + srow) * E_ + h * 128 + lane * 4] = ov;
    }
}

// ================================ launch =====================================
extern "C" void kernel_launch(void* const* d_in, const int* in_sizes, int n_in,
                              void* d_out, int out_size) {
    const float* x   = (const float*)d_in[0];
    const float* Wq  = (const float*)d_in[1];
    const float* bq  = (const float*)d_in[2];
    const float* Wkv = (const float*)d_in[3];
    const float* bkv = (const float*)d_in[4];
    const float* Wo  = (const float*)d_in[5];
    float* out = (float*)d_out;

    float *qb, *kvb, *ob;
    cudaGetSymbolAddress((void**)&qb,  g_qproj);
    cudaGetSymbolAddress((void**)&kvb, g_kvproj);
    cudaGetSymbolAddress((void**)&ob,  g_attno);

    // Q projection: [4096,2048] = x @ Wq^T + bq
    sgemm_nt<<<dim3(E_ / 128, M_ / 128), 256>>>(x, Wq, bq, qb, M_, E_, E_);
    // KV projection: [4096,1024]
    sgemm_nt<<<dim3(KVN_ / 128, M_ / 128), 256>>>(x, Wkv, bkv, kvb, M_, KVN_, E_);

    // RoPE on Q and K
    {
        int totq = M_ * H_ * 64;
        rope_kernel<<<(totq + 255) / 256, 256>>>(qb, H_, E_);
        int totk = M_ * KVH_ * 64;
        rope_kernel<<<(totk + 255) / 256, 256>>>(kvb, KVH_, KVN_);
    }

    // Flash attention
    {
        size_t smem = FLASH_SMEM_FLOATS * sizeof(float);
        static bool attr_set = false;
        cudaFuncSetAttribute(flash_kernel,
                             cudaFuncAttributeMaxDynamicSharedMemorySize,
                             (int)smem);
        (void)attr_set;
        flash_kernel<<<dim3(S_ / 32, B_ * H_), 256, smem>>>(qb, kvb, ob);
    }

    // Output projection: out = attno @ Wo^T
    sgemm_nt<<<dim3(E_ / 128, M_ / 128), 256>>>(ob, Wo, nullptr, out, M_, E_, E_);
}

// round 5
// speedup vs baseline: 1.3481x; 1.3481x over previous
#include <cuda_runtime.h>
#include <cuda_bf16.h>
#include <math.h>
#include <stdint.h>

// Problem constants
#define B_   2
#define S_   2048
#define E_   2048
#define H_   16
#define KVH_ 4
#define D_   128
#define M_   (B_ * S_)        // 4096 rows
#define KVN_ (2 * KVH_ * D_)  // 1024

// ---------------- scratch (device globals; no allocs allowed) ----------------
__device__ float g_qproj[(size_t)M_ * E_];
__device__ float g_kvproj[(size_t)M_ * KVN_];
__device__ float g_attno[(size_t)M_ * E_];

__device__ unsigned short g_xhi[(size_t)M_ * E_];
__device__ unsigned short g_xlo[(size_t)M_ * E_];
__device__ unsigned short g_wqhi[(size_t)E_ * E_];
__device__ unsigned short g_wqlo[(size_t)E_ * E_];
__device__ unsigned short g_wkvhi[(size_t)KVN_ * E_];
__device__ unsigned short g_wkvlo[(size_t)KVN_ * E_];
__device__ unsigned short g_wohi[(size_t)E_ * E_];
__device__ unsigned short g_wolo[(size_t)E_ * E_];
__device__ unsigned short g_aohi[(size_t)M_ * E_];
__device__ unsigned short g_aolo[(size_t)M_ * E_];

// ============================ PTX helpers ====================================
__device__ __forceinline__ uint32_t smem_u32(const void* p) {
    uint32_t a;
    asm("{ .reg .u64 t; cvta.to.shared.u64 t, %1; cvt.u32.u64 %0, t; }"
        : "=r"(a) : "l"(p));
    return a;
}
__device__ __forceinline__ void cp_async16(uint32_t dst, const void* src) {
    asm volatile("cp.async.cg.shared.global [%0], [%1], 16;"
                 :: "r"(dst), "l"(src) : "memory");
}
__device__ __forceinline__ void cp_commit() {
    asm volatile("cp.async.commit_group;" ::: "memory");
}
template <int N>
__device__ __forceinline__ void cp_wait() {
    asm volatile("cp.async.wait_group %0;" :: "n"(N) : "memory");
}
__device__ __forceinline__ void ldmx4(uint32_t& r0, uint32_t& r1, uint32_t& r2,
                                      uint32_t& r3, uint32_t addr) {
    asm volatile("ldmatrix.sync.aligned.m8n8.x4.shared.b16 {%0,%1,%2,%3}, [%4];"
                 : "=r"(r0), "=r"(r1), "=r"(r2), "=r"(r3) : "r"(addr));
}
__device__ __forceinline__ void mma_bf16(float& d0, float& d1, float& d2, float& d3,
                                         uint32_t a0, uint32_t a1, uint32_t a2,
                                         uint32_t a3, uint32_t b0, uint32_t b1) {
    asm volatile(
        "mma.sync.aligned.m16n8k16.row.col.f32.bf16.bf16.f32 "
        "{%0,%1,%2,%3}, {%4,%5,%6,%7}, {%8,%9}, {%0,%1,%2,%3};"
        : "+f"(d0), "+f"(d1), "+f"(d2), "+f"(d3)
        : "r"(a0), "r"(a1), "r"(a2), "r"(a3), "r"(b0), "r"(b1));
}

// ====================== fp32 -> bf16 hi/lo split kernel ======================
__device__ __forceinline__ void split1(float x, unsigned short& h, unsigned short& l) {
    __nv_bfloat16 bh = __float2bfloat16_rn(x);
    float r = x - __bfloat162float(bh);
    __nv_bfloat16 bl = __float2bfloat16_rn(r);
    h = __bfloat16_as_ushort(bh);
    l = __bfloat16_as_ushort(bl);
}
__global__ void __launch_bounds__(256) split_bf16(const float* __restrict__ in,
                                                  unsigned short* __restrict__ hi,
                                                  unsigned short* __restrict__ lo,
                                                  int n4) {
    int i = blockIdx.x * blockDim.x + threadIdx.x;
    if (i >= n4) return;
    float4 v = ((const float4*)in)[i];
    ushort4 h, l;
    split1(v.x, h.x, l.x);
    split1(v.y, h.y, l.y);
    split1(v.z, h.z, l.z);
    split1(v.w, h.w, l.w);
    ((ushort4*)hi)[i] = h;
    ((ushort4*)lo)[i] = l;
}

// =============== HMMA GEMM: C = A@W^T (+bias), 3x bf16 split =================
// A_{hi,lo}: [M,K] bf16 row-major; W_{hi,lo}: [N,K] bf16 row-major; C: [M,N] f32.
// CTA tile 128x128, BK=32 bf16, cp.async double buffer, mma.sync m16n8k16.
// smem row stride 80B (32 bf16 + 16B pad) -> conflict-free ldmatrix.
#define GS_STRIDE 80
#define GS_BUF    (128 * GS_STRIDE)          // 10240 B per tile buffer

__global__ void __launch_bounds__(256)
gemm_hmma_x3(const unsigned short* __restrict__ Ahi, const unsigned short* __restrict__ Alo,
             const unsigned short* __restrict__ Bhi, const unsigned short* __restrict__ Blo,
             const float* __restrict__ bias, float* __restrict__ C,
             int M, int N, int K) {
    __shared__ __align__(16) unsigned char smem[4 * GS_BUF];   // A0 A1 B0 B1
    const uint32_t sb = smem_u32(smem);
    const int tid = threadIdx.x;
    const int wid = tid >> 5, lane = tid & 31;
    const int wm = wid & 3;          // 0..3 : 32-row band
    const int wn = wid >> 2;         // 0..1 : 64-col band
    const int m0 = blockIdx.y * 128, n0 = blockIdx.x * 128;

    // loader mapping: 512 16B units per tile; thread handles units tid, tid+256
    const int NCH = 3 * (K >> 5);    // total BK=32 chunks over 3 segments
    const int segC = K >> 5;         // chunks per segment

    float acc[2][8][4];
#pragma unroll
    for (int mt = 0; mt < 2; mt++)
#pragma unroll
        for (int nt = 0; nt < 8; nt++)
#pragma unroll
            for (int i = 0; i < 4; i++) acc[mt][nt][i] = 0.f;

    auto issue = [&](int c, int buf) {
        const int seg = c / segC;
        const int kk = (c % segC) << 5;                 // k offset (elements)
        const unsigned short* Ap = (seg == 2) ? Alo : Ahi;
        const unsigned short* Bp = (seg == 1) ? Blo : Bhi;
#pragma unroll
        for (int h = 0; h < 2; h++) {
            const int u = tid + h * 256;                // 0..511
            const int row = u >> 2;
            const int kb = (u & 3) << 3;                // element offset in k (8 bf16=16B)
            cp_async16(sb + buf * GS_BUF + row * GS_STRIDE + (kb << 1),
                       Ap + (size_t)(m0 + row) * K + kk + kb);
            cp_async16(sb + 2 * GS_BUF + buf * GS_BUF + row * GS_STRIDE + (kb << 1),
                       Bp + (size_t)(n0 + row) * K + kk + kb);
        }
        cp_commit();
    };

    issue(0, 0);
    int buf = 0;
    for (int c = 0; c < NCH; c++) {
        if (c + 1 < NCH) { issue(c + 1, buf ^ 1); cp_wait<1>(); }
        else             { cp_wait<0>(); }
        __syncthreads();

        const uint32_t abase = sb + buf * GS_BUF;
        const uint32_t bbase = sb + 2 * GS_BUF + buf * GS_BUF;
#pragma unroll
        for (int ks = 0; ks < 2; ks++) {                // k-step of 16
            const int kbyte = ks * 32;
            uint32_t a[2][4];
#pragma unroll
            for (int mt = 0; mt < 2; mt++) {
                const int row = wm * 32 + mt * 16 + (lane & 15);
                ldmx4(a[mt][0], a[mt][1], a[mt][2], a[mt][3],
                      abase + row * GS_STRIDE + kbyte + ((lane >> 4) << 4));
            }
            uint32_t b[8][2];
#pragma unroll
            for (int np = 0; np < 4; np++) {            // n-tile pair (16 cols)
                const int row = wn * 64 + np * 16 + (((lane >> 4) & 1) << 3) + (lane & 7);
                uint32_t r0, r1, r2, r3;
                ldmx4(r0, r1, r2, r3,
                      bbase + row * GS_STRIDE + kbyte + (((lane >> 3) & 1) << 4));
                b[np * 2][0] = r0; b[np * 2][1] = r1;
                b[np * 2 + 1][0] = r2; b[np * 2 + 1][1] = r3;
            }
#pragma unroll
            for (int mt = 0; mt < 2; mt++)
#pragma unroll
                for (int nt = 0; nt < 8; nt++)
                    mma_bf16(acc[mt][nt][0], acc[mt][nt][1],
                             acc[mt][nt][2], acc[mt][nt][3],
                             a[mt][0], a[mt][1], a[mt][2], a[mt][3],
                             b[nt][0], b[nt][1]);
        }
        __syncthreads();
        buf ^= 1;
    }

    // epilogue: fragment -> gmem (+bias)
    const int mrow = m0 + wm * 32 + (lane >> 2);
    const int ncol0 = n0 + wn * 64 + ((lane & 3) << 1);
#pragma unroll
    for (int mt = 0; mt < 2; mt++) {
#pragma unroll
        for (int nt = 0; nt < 8; nt++) {
            const int n = ncol0 + nt * 8;
            float b0 = bias ? bias[n] : 0.f;
            float b1 = bias ? bias[n + 1] : 0.f;
            float2 v0 = make_float2(acc[mt][nt][0] + b0, acc[mt][nt][1] + b1);
            float2 v1 = make_float2(acc[mt][nt][2] + b0, acc[mt][nt][3] + b1);
            *(float2*)&C[(size_t)(mrow + mt * 16) * N + n] = v0;
            *(float2*)&C[(size_t)(mrow + mt * 16 + 8) * N + n] = v1;
        }
    }
}

// ================================ RoPE (in place) ============================
__global__ void rope_kernel(float* __restrict__ t, int nHeads, int rowStride) {
    int idx = blockIdx.x * blockDim.x + threadIdx.x;
    int total = M_ * nHeads * 64;
    if (idx >= total) return;
    int i = idx & 63;
    int h = (idx >> 6) % nHeads;
    int m = idx / (64 * nHeads);
    int s = m & (S_ - 1);
    float inv = powf(10000.0f, -(float)i * (1.0f / 64.0f));
    float fr = (float)s * inv;
    float sn, cs;
    sincosf(fr, &sn, &cs);
    float* p = t + (size_t)m * rowStride + h * 128 + i;
    float v1 = p[0], v2 = p[64];
    p[0]  = v1 * cs - v2 * sn;
    p[64] = v2 * cs + v1 * sn;
}

// ============================ Flash attention ================================
#define BKf 64
#define KT_STRIDE 65
#define FLASH_SMEM_FLOATS (32 * 128 + 128 * KT_STRIDE + 64 * 128 + 8 * 4 * 64)

extern __shared__ float fsm[];
__global__ void __launch_bounds__(256) flash_kernel(const float* __restrict__ Q,
                                                    const float* __restrict__ KV,
                                                    float* __restrict__ O) {
    float* q_s = fsm;
    float* Kt  = q_s + 32 * 128;
    float* Vs  = Kt + 128 * KT_STRIDE;
    float* p_s = Vs + 64 * 128;

    const int tid = threadIdx.x;
    const int warp = tid >> 5, lane = tid & 31;
    const int bh = blockIdx.y;
    const int b = bh >> 4, h = bh & 15;
    const int kvh = h >> 2;
    const int q0 = blockIdx.x * 32;
    const float scale = 0.08838834764831845f;

    for (int i = tid; i < 32 * (D_ / 4); i += 256) {
        int r = i >> 5;
        int c = (i & 31) << 2;
        *(float4*)&q_s[r * D_ + c] =
            *(const float4*)&Q[(size_t)(b * S_ + q0 + r) * E_ + h * 128 + c];
    }

    float m_r[4], l_r[4], o_acc[4][4];
#pragma unroll
    for (int r = 0; r < 4; r++) {
        m_r[r] = -1e30f; l_r[r] = 0.f;
#pragma unroll
        for (int i = 0; i < 4; i++) o_acc[r][i] = 0.f;
    }

    const float* Kbase = KV + (size_t)b * S_ * KVN_ + kvh * 128;
    const float* Vbase = KV + (size_t)b * S_ * KVN_ + KVH_ * 128 + kvh * 128;

    for (int kt = 0; kt < S_; kt += BKf) {
        __syncthreads();
#pragma unroll
        for (int it = 0; it < 8; it++) {
            int li = tid + it * 256;
            int j = li >> 5;
            int d = (li & 31) << 2;
            float4 k4 = *(const float4*)&Kbase[(size_t)(kt + j) * KVN_ + d];
            Kt[(d + 0) * KT_STRIDE + j] = k4.x;
            Kt[(d + 1) * KT_STRIDE + j] = k4.y;
            Kt[(d + 2) * KT_STRIDE + j] = k4.z;
            Kt[(d + 3) * KT_STRIDE + j] = k4.w;
            float4 v4 = *(const float4*)&Vbase[(size_t)(kt + j) * KVN_ + d];
            *(float4*)&Vs[j * D_ + d] = v4;
        }
        __syncthreads();

        float s[4][2];
#pragma unroll
        for (int r = 0; r < 4; r++) { s[r][0] = 0.f; s[r][1] = 0.f; }
#pragma unroll
        for (int d4 = 0; d4 < D_; d4 += 4) {
            float k0[4], k1[4];
#pragma unroll
            for (int i = 0; i < 4; i++) {
                k0[i] = Kt[(d4 + i) * KT_STRIDE + lane];
                k1[i] = Kt[(d4 + i) * KT_STRIDE + lane + 32];
            }
#pragma unroll
            for (int r = 0; r < 4; r++) {
                float4 qv = *(float4*)&q_s[(warp * 4 + r) * D_ + d4];
                s[r][0] += qv.x * k0[0] + qv.y * k0[1] + qv.z * k0[2] + qv.w * k0[3];
                s[r][1] += qv.x * k1[0] + qv.y * k1[1] + qv.z * k1[2] + qv.w * k1[3];
            }
        }
#pragma unroll
        for (int r = 0; r < 4; r++) {
            float s0 = s[r][0] * scale, s1 = s[r][1] * scale;
            float mx = fmaxf(s0, s1);
#pragma unroll
            for (int off = 16; off; off >>= 1)
                mx = fmaxf(mx, __shfl_xor_sync(0xffffffffu, mx, off));
            float mnew = fmaxf(m_r[r], mx);
            float p0 = expf(s0 - mnew), p1 = expf(s1 - mnew);
            float corr = expf(m_r[r] - mnew);
            float ps = p0 + p1;
#pragma unroll
            for (int off = 16; off; off >>= 1)
                ps += __shfl_xor_sync(0xffffffffu, ps, off);
            l_r[r] = l_r[r] * corr + ps;
            m_r[r] = mnew;
#pragma unroll
            for (int i = 0; i < 4; i++) o_acc[r][i] *= corr;
            p_s[(warp * 4 + r) * 64 + lane] = p0;
            p_s[(warp * 4 + r) * 64 + lane + 32] = p1;
        }
        __syncwarp();
#pragma unroll 4
        for (int j = 0; j < BKf; j++) {
            float4 vv = *(float4*)&Vs[j * D_ + lane * 4];
#pragma unroll
            for (int r = 0; r < 4; r++) {
                float pj = p_s[(warp * 4 + r) * 64 + j];
                o_acc[r][0] += pj * vv.x;
                o_acc[r][1] += pj * vv.y;
                o_acc[r][2] += pj * vv.z;
                o_acc[r][3] += pj * vv.w;
            }
        }
    }
#pragma unroll
    for (int r = 0; r < 4; r++) {
        float inv = 1.f / l_r[r];
        float4 ov;
        ov.x = o_acc[r][0] * inv; ov.y = o_acc[r][1] * inv;
        ov.z = o_acc[r][2] * inv; ov.w = o_acc[r][3] * inv;
        int srow = q0 + warp * 4 + r;
        *(float4*)&O[(size_t)(b * S_ + srow) * E_ + h * 128 + lane * 4] = ov;
    }
}

// ================================ launch =====================================
extern "C" void kernel_launch(void* const* d_in, const int* in_sizes, int n_in,
                              void* d_out, int out_size) {
    const float* x   = (const float*)d_in[0];
    const float* Wq  = (const float*)d_in[1];
    const float* bq  = (const float*)d_in[2];
    const float* Wkv = (const float*)d_in[3];
    const float* bkv = (const float*)d_in[4];
    const float* Wo  = (const float*)d_in[5];
    float* out = (float*)d_out;

    float *qb, *kvb, *ob;
    cudaGetSymbolAddress((void**)&qb,  g_qproj);
    cudaGetSymbolAddress((void**)&kvb, g_kvproj);
    cudaGetSymbolAddress((void**)&ob,  g_attno);
    unsigned short *xhi, *xlo, *wqhi, *wqlo, *wkvhi, *wkvlo, *wohi, *wolo, *aohi, *aolo;
    cudaGetSymbolAddress((void**)&xhi,  g_xhi);
    cudaGetSymbolAddress((void**)&xlo,  g_xlo);
    cudaGetSymbolAddress((void**)&wqhi, g_wqhi);
    cudaGetSymbolAddress((void**)&wqlo, g_wqlo);
    cudaGetSymbolAddress((void**)&wkvhi, g_wkvhi);
    cudaGetSymbolAddress((void**)&wkvlo, g_wkvlo);
    cudaGetSymbolAddress((void**)&wohi, g_wohi);
    cudaGetSymbolAddress((void**)&wolo, g_wolo);
    cudaGetSymbolAddress((void**)&aohi, g_aohi);
    cudaGetSymbolAddress((void**)&aolo, g_aolo);

    // fp32 -> bf16 hi/lo splits
    {
        int n4;
        n4 = M_ * E_ / 4;   split_bf16<<<(n4 + 255) / 256, 256>>>(x,   xhi,  xlo,  n4);
        n4 = E_ * E_ / 4;   split_bf16<<<(n4 + 255) / 256, 256>>>(Wq,  wqhi, wqlo, n4);
        n4 = KVN_ * E_ / 4; split_bf16<<<(n4 + 255) / 256, 256>>>(Wkv, wkvhi, wkvlo, n4);
        n4 = E_ * E_ / 4;   split_bf16<<<(n4 + 255) / 256, 256>>>(Wo,  wohi, wolo, n4);
    }

    // Q projection: [4096,2048]
    gemm_hmma_x3<<<dim3(E_ / 128, M_ / 128), 256>>>(
        xhi, xlo, wqhi, wqlo, bq, qb, M_, E_, E_);
    // KV projection: [4096,1024]
    gemm_hmma_x3<<<dim3(KVN_ / 128, M_ / 128), 256>>>(
        xhi, xlo, wkvhi, wkvlo, bkv, kvb, M_, KVN_, E_);

    // RoPE on Q and K
    {
        int totq = M_ * H_ * 64;
        rope_kernel<<<(totq + 255) / 256, 256>>>(qb, H_, E_);
        int totk = M_ * KVH_ * 64;
        rope_kernel<<<(totk + 255) / 256, 256>>>(kvb, KVH_, KVN_);
    }

    // Flash attention
    {
        size_t smem = FLASH_SMEM_FLOATS * sizeof(float);
        cudaFuncSetAttribute(flash_kernel,
                             cudaFuncAttributeMaxDynamicSharedMemorySize, (int)smem);
        flash_kernel<<<dim3(S_ / 32, B_ * H_), 256, smem>>>(qb, kvb, ob);
    }

    // split attention output, then O projection
    {
        int n4 = M_ * E_ / 4;
        split_bf16<<<(n4 + 255) / 256, 256>>>(ob, aohi, aolo, n4);
    }
    gemm_hmma_x3<<<dim3(E_ / 128, M_ / 128), 256>>>(
        aohi, aolo, wohi, wolo, nullptr, out, M_, E_, E_);
}

// round 6
// speedup vs baseline: 2.8025x; 2.0788x over previous
#include <cuda_runtime.h>
#include <cuda_bf16.h>
#include <math.h>
#include <stdint.h>

// Problem constants
#define B_   2
#define S_   2048
#define E_   2048
#define H_   16
#define KVH_ 4
#define D_   128
#define M_   (B_ * S_)        // 4096 rows
#define KVN_ (2 * KVH_ * D_)  // 1024

// ---------------- scratch (device globals; no allocs allowed) ----------------
__device__ float g_qproj[(size_t)M_ * E_];
__device__ float g_kvproj[(size_t)M_ * KVN_];
__device__ float g_attno[(size_t)M_ * E_];

__device__ unsigned short g_xhi[(size_t)M_ * E_];
__device__ unsigned short g_xlo[(size_t)M_ * E_];
__device__ unsigned short g_wqhi[(size_t)E_ * E_];
__device__ unsigned short g_wqlo[(size_t)E_ * E_];
__device__ unsigned short g_wkvhi[(size_t)KVN_ * E_];
__device__ unsigned short g_wkvlo[(size_t)KVN_ * E_];
__device__ unsigned short g_wohi[(size_t)E_ * E_];
__device__ unsigned short g_wolo[(size_t)E_ * E_];
__device__ unsigned short g_aohi[(size_t)M_ * E_];
__device__ unsigned short g_aolo[(size_t)M_ * E_];
// flash operands (bf16 hi/lo)
__device__ unsigned short g_qhi[(size_t)M_ * E_];
__device__ unsigned short g_qlo[(size_t)M_ * E_];
__device__ unsigned short g_kvphi[(size_t)M_ * KVN_];
__device__ unsigned short g_kvplo[(size_t)M_ * KVN_];
__device__ unsigned short g_vthi[(size_t)B_ * KVH_ * D_ * S_];
__device__ unsigned short g_vtlo[(size_t)B_ * KVH_ * D_ * S_];

// ============================ PTX helpers ====================================
__device__ __forceinline__ uint32_t smem_u32(const void* p) {
    uint32_t a;
    asm("{ .reg .u64 t; cvta.to.shared.u64 t, %1; cvt.u32.u64 %0, t; }"
        : "=r"(a) : "l"(p));
    return a;
}
__device__ __forceinline__ void cp_async16(uint32_t dst, const void* src) {
    asm volatile("cp.async.cg.shared.global [%0], [%1], 16;"
                 :: "r"(dst), "l"(src) : "memory");
}
__device__ __forceinline__ void cp_commit() {
    asm volatile("cp.async.commit_group;" ::: "memory");
}
template <int N>
__device__ __forceinline__ void cp_wait() {
    asm volatile("cp.async.wait_group %0;" :: "n"(N) : "memory");
}
__device__ __forceinline__ void ldmx4(uint32_t& r0, uint32_t& r1, uint32_t& r2,
                                      uint32_t& r3, uint32_t addr) {
    asm volatile("ldmatrix.sync.aligned.m8n8.x4.shared.b16 {%0,%1,%2,%3}, [%4];"
                 : "=r"(r0), "=r"(r1), "=r"(r2), "=r"(r3) : "r"(addr));
}
__device__ __forceinline__ void mma_bf16(float& d0, float& d1, float& d2, float& d3,
                                         uint32_t a0, uint32_t a1, uint32_t a2,
                                         uint32_t a3, uint32_t b0, uint32_t b1) {
    asm volatile(
        "mma.sync.aligned.m16n8k16.row.col.f32.bf16.bf16.f32 "
        "{%0,%1,%2,%3}, {%4,%5,%6,%7}, {%8,%9}, {%0,%1,%2,%3};"
        : "+f"(d0), "+f"(d1), "+f"(d2), "+f"(d3)
        : "r"(a0), "r"(a1), "r"(a2), "r"(a3), "r"(b0), "r"(b1));
}
__device__ __forceinline__ float ex2f(float x) {
    float y;
    asm("ex2.approx.ftz.f32 %0, %1;" : "=f"(y) : "f"(x));
    return y;
}
__device__ __forceinline__ uint32_t packbf(float a, float b) {
    __nv_bfloat162 t = __floats2bfloat162_rn(a, b);
    return *(uint32_t*)&t;
}

// ====================== fp32 -> bf16 hi/lo split kernel ======================
__device__ __forceinline__ void split1(float x, unsigned short& h, unsigned short& l) {
    __nv_bfloat16 bh = __float2bfloat16_rn(x);
    float r = x - __bfloat162float(bh);
    __nv_bfloat16 bl = __float2bfloat16_rn(r);
    h = __bfloat16_as_ushort(bh);
    l = __bfloat16_as_ushort(bl);
}
__global__ void __launch_bounds__(256) split_bf16(const float* __restrict__ in,
                                                  unsigned short* __restrict__ hi,
                                                  unsigned short* __restrict__ lo,
                                                  int n4) {
    int i = blockIdx.x * blockDim.x + threadIdx.x;
    if (i >= n4) return;
    float4 v = ((const float4*)in)[i];
    ushort4 h, l;
    split1(v.x, h.x, l.x);
    split1(v.y, h.y, l.y);
    split1(v.z, h.z, l.z);
    split1(v.w, h.w, l.w);
    ((ushort4*)hi)[i] = h;
    ((ushort4*)lo)[i] = l;
}

// ============ V transpose + split: kvproj V-part -> VT[d, s] bf16 ============
__global__ void __launch_bounds__(256) vtrans_split(const float* __restrict__ kv,
                                                    unsigned short* __restrict__ vthi,
                                                    unsigned short* __restrict__ vtlo) {
    __shared__ float t[32][33];
    const int s0 = blockIdx.x * 32, d0 = blockIdx.y * 32;
    const int bk = blockIdx.z;            // b*KVH_+kvh
    const int b = bk >> 2, kvh = bk & 3;
    const int tx = threadIdx.x & 31, ty = threadIdx.x >> 5;  // 32 x 8
#pragma unroll
    for (int i = 0; i < 4; i++) {
        int s = s0 + ty + i * 8;
        t[ty + i * 8][tx] =
            kv[(size_t)(b * S_ + s) * KVN_ + KVH_ * D_ + kvh * 128 + d0 + tx];
    }
    __syncthreads();
#pragma unroll
    for (int i = 0; i < 4; i++) {
        int d = d0 + ty + i * 8;
        float v = t[tx][ty + i * 8];
        unsigned short hi, lo;
        split1(v, hi, lo);
        size_t o = ((size_t)bk * 128 + d) * S_ + s0 + tx;
        vthi[o] = hi;
        vtlo[o] = lo;
    }
}

// =============== HMMA GEMM: C = A@W^T (+bias), 3x bf16 split =================
#define GS_STRIDE 80
#define GS_BUF    (128 * GS_STRIDE)

__global__ void __launch_bounds__(256)
gemm_hmma_x3(const unsigned short* __restrict__ Ahi, const unsigned short* __restrict__ Alo,
             const unsigned short* __restrict__ Bhi, const unsigned short* __restrict__ Blo,
             const float* __restrict__ bias, float* __restrict__ C,
             int M, int N, int K) {
    __shared__ __align__(16) unsigned char smem[4 * GS_BUF];
    const uint32_t sb = smem_u32(smem);
    const int tid = threadIdx.x;
    const int wid = tid >> 5, lane = tid & 31;
    const int wm = wid & 3;
    const int wn = wid >> 2;
    const int m0 = blockIdx.y * 128, n0 = blockIdx.x * 128;

    const int NCH = 3 * (K >> 5);
    const int segC = K >> 5;

    float acc[2][8][4];
#pragma unroll
    for (int mt = 0; mt < 2; mt++)
#pragma unroll
        for (int nt = 0; nt < 8; nt++)
#pragma unroll
            for (int i = 0; i < 4; i++) acc[mt][nt][i] = 0.f;

    auto issue = [&](int c, int buf) {
        const int seg = c / segC;
        const int kk = (c % segC) << 5;
        const unsigned short* Ap = (seg == 2) ? Alo : Ahi;
        const unsigned short* Bp = (seg == 1) ? Blo : Bhi;
#pragma unroll
        for (int h = 0; h < 2; h++) {
            const int u = tid + h * 256;
            const int row = u >> 2;
            const int kb = (u & 3) << 3;
            cp_async16(sb + buf * GS_BUF + row * GS_STRIDE + (kb << 1),
                       Ap + (size_t)(m0 + row) * K + kk + kb);
            cp_async16(sb + 2 * GS_BUF + buf * GS_BUF + row * GS_STRIDE + (kb << 1),
                       Bp + (size_t)(n0 + row) * K + kk + kb);
        }
        cp_commit();
    };

    issue(0, 0);
    int buf = 0;
    for (int c = 0; c < NCH; c++) {
        if (c + 1 < NCH) { issue(c + 1, buf ^ 1); cp_wait<1>(); }
        else             { cp_wait<0>(); }
        __syncthreads();

        const uint32_t abase = sb + buf * GS_BUF;
        const uint32_t bbase = sb + 2 * GS_BUF + buf * GS_BUF;
#pragma unroll
        for (int ks = 0; ks < 2; ks++) {
            const int kbyte = ks * 32;
            uint32_t a[2][4];
#pragma unroll
            for (int mt = 0; mt < 2; mt++) {
                const int row = wm * 32 + mt * 16 + (lane & 15);
                ldmx4(a[mt][0], a[mt][1], a[mt][2], a[mt][3],
                      abase + row * GS_STRIDE + kbyte + ((lane >> 4) << 4));
            }
            uint32_t b[8][2];
#pragma unroll
            for (int np = 0; np < 4; np++) {
                const int row = wn * 64 + np * 16 + (((lane >> 4) & 1) << 3) + (lane & 7);
                uint32_t r0, r1, r2, r3;
                ldmx4(r0, r1, r2, r3,
                      bbase + row * GS_STRIDE + kbyte + (((lane >> 3) & 1) << 4));
                b[np * 2][0] = r0; b[np * 2][1] = r1;
                b[np * 2 + 1][0] = r2; b[np * 2 + 1][1] = r3;
            }
#pragma unroll
            for (int mt = 0; mt < 2; mt++)
#pragma unroll
                for (int nt = 0; nt < 8; nt++)
                    mma_bf16(acc[mt][nt][0], acc[mt][nt][1],
                             acc[mt][nt][2], acc[mt][nt][3],
                             a[mt][0], a[mt][1], a[mt][2], a[mt][3],
                             b[nt][0], b[nt][1]);
        }
        __syncthreads();
        buf ^= 1;
    }

    const int mrow = m0 + wm * 32 + (lane >> 2);
    const int ncol0 = n0 + wn * 64 + ((lane & 3) << 1);
#pragma unroll
    for (int mt = 0; mt < 2; mt++) {
#pragma unroll
        for (int nt = 0; nt < 8; nt++) {
            const int n = ncol0 + nt * 8;
            float b0 = bias ? bias[n] : 0.f;
            float b1 = bias ? bias[n + 1] : 0.f;
            float2 v0 = make_float2(acc[mt][nt][0] + b0, acc[mt][nt][1] + b1);
            float2 v1 = make_float2(acc[mt][nt][2] + b0, acc[mt][nt][3] + b1);
            *(float2*)&C[(size_t)(mrow + mt * 16) * N + n] = v0;
            *(float2*)&C[(size_t)(mrow + mt * 16 + 8) * N + n] = v1;
        }
    }
}

// ================================ RoPE (in place) ============================
__global__ void rope_kernel(float* __restrict__ t, int nHeads, int rowStride) {
    int idx = blockIdx.x * blockDim.x + threadIdx.x;
    int total = M_ * nHeads * 64;
    if (idx >= total) return;
    int i = idx & 63;
    int h = (idx >> 6) % nHeads;
    int m = idx / (64 * nHeads);
    int s = m & (S_ - 1);
    float inv = powf(10000.0f, -(float)i * (1.0f / 64.0f));
    float fr = (float)s * inv;
    float sn, cs;
    sincosf(fr, &sn, &cs);
    float* p = t + (size_t)m * rowStride + h * 128 + i;
    float v1 = p[0], v2 = p[64];
    p[0]  = v1 * cs - v2 * sn;
    p[64] = v2 * cs + v1 * sn;
}

// ===================== HMMA flash attention (3x bf16 split) ==================
// CTA: 128 q rows, 8 warps (16 rows each). KV tile BN=128. Online softmax.
// Q[hi/lo], K[hi/lo] from row-major [rows, d]; V via VT[hi/lo] [d, s].
#define FS_STRIDE 272
#define FS_TILE   (128 * FS_STRIDE)          // 34816 B
#define FQHI 0
#define FQLO (FS_TILE)
#define FKHI (2 * FS_TILE)
#define FKLO (3 * FS_TILE)
#define FVHI (4 * FS_TILE)
#define FVLO (5 * FS_TILE)
#define FS_SMEM (6 * FS_TILE)                // 208896 B

__global__ void __launch_bounds__(256)
flash_hmma(const unsigned short* __restrict__ qhi, const unsigned short* __restrict__ qlo,
           const unsigned short* __restrict__ khi, const unsigned short* __restrict__ klo,
           const unsigned short* __restrict__ vthi, const unsigned short* __restrict__ vtlo,
           float* __restrict__ O) {
    extern __shared__ __align__(16) unsigned char fsm2[];
    const uint32_t sb = smem_u32(fsm2);
    const int tid = threadIdx.x;
    const int w = tid >> 5, lane = tid & 31;
    const int bh = blockIdx.y;
    const int b = bh >> 4, h = bh & 15;
    const int kvh = h >> 2;
    const int q0 = blockIdx.x * 128;
    const float scale2 = 0.127518795f;       // (1/sqrt(128)) * log2(e)

    const unsigned short* qhp = qhi + (size_t)(b * S_ + q0) * E_ + h * 128;
    const unsigned short* qlp = qlo + (size_t)(b * S_ + q0) * E_ + h * 128;
    const unsigned short* khp = khi + (size_t)b * S_ * KVN_ + kvh * 128;
    const unsigned short* klp = klo + (size_t)b * S_ * KVN_ + kvh * 128;
    const unsigned short* vhp = vthi + ((size_t)(b * KVH_ + kvh) * 128) * S_;
    const unsigned short* vlp = vtlo + ((size_t)(b * KVH_ + kvh) * 128) * S_;

    auto load_tile = [&](uint32_t dst, const unsigned short* src, int rowStrideElems) {
#pragma unroll
        for (int it = 0; it < 8; it++) {
            int u = tid + it * 256;          // 0..2047
            int row = u >> 4;
            int cb = (u & 15) << 4;          // byte col
            cp_async16(sb + dst + row * FS_STRIDE + cb,
                       (const char*)src + (size_t)row * rowStrideElems * 2 + cb);
        }
    };

    // initial loads: Q (persistent) + tile 0 of K/VT
    load_tile(FQHI, qhp, E_);
    load_tile(FQLO, qlp, E_);
    load_tile(FKHI, khp, KVN_);
    load_tile(FKLO, klp, KVN_);
    load_tile(FVHI, vhp, S_);
    load_tile(FVLO, vlp, S_);
    cp_commit();
    cp_wait<0>();
    __syncthreads();

    float oacc[16][4];
#pragma unroll
    for (int nt = 0; nt < 16; nt++)
#pragma unroll
        for (int i = 0; i < 4; i++) oacc[nt][i] = 0.f;
    float m0 = -1e30f, m1 = -1e30f, l0 = 0.f, l1 = 0.f;

    // fragment addressing (constant per thread)
    const int arow = w * 16 + (lane & 15);
    const uint32_t aoff_base = arow * FS_STRIDE + ((lane >> 4) << 4);
    const int brow = (((lane >> 4) & 1) << 3) + (lane & 7);
    const uint32_t boff_base = brow * FS_STRIDE + (((lane >> 3) & 1) << 4);

    for (int kt = 0; kt < S_ / 128; kt++) {
        float sacc[16][4];
#pragma unroll
        for (int nt = 0; nt < 16; nt++)
#pragma unroll
            for (int i = 0; i < 4; i++) sacc[nt][i] = 0.f;

        // ---- S = Q K^T (3-way split) ----
#pragma unroll
        for (int ks = 0; ks < 8; ks++) {
            uint32_t ah[4], al[4];
            ldmx4(ah[0], ah[1], ah[2], ah[3], sb + FQHI + aoff_base + ks * 32);
            ldmx4(al[0], al[1], al[2], al[3], sb + FQLO + aoff_base + ks * 32);
#pragma unroll
            for (int np = 0; np < 8; np++) {
                const uint32_t bo = boff_base + np * 16 * FS_STRIDE + ks * 32;
                uint32_t bh0, bh1, bh2, bh3, bl0, bl1, bl2, bl3;
                ldmx4(bh0, bh1, bh2, bh3, sb + FKHI + bo);
                ldmx4(bl0, bl1, bl2, bl3, sb + FKLO + bo);
                float* s0 = sacc[np * 2];
                float* s1 = sacc[np * 2 + 1];
                mma_bf16(s0[0], s0[1], s0[2], s0[3], ah[0], ah[1], ah[2], ah[3], bh0, bh1);
                mma_bf16(s1[0], s1[1], s1[2], s1[3], ah[0], ah[1], ah[2], ah[3], bh2, bh3);
                mma_bf16(s0[0], s0[1], s0[2], s0[3], ah[0], ah[1], ah[2], ah[3], bl0, bl1);
                mma_bf16(s1[0], s1[1], s1[2], s1[3], ah[0], ah[1], ah[2], ah[3], bl2, bl3);
                mma_bf16(s0[0], s0[1], s0[2], s0[3], al[0], al[1], al[2], al[3], bh0, bh1);
                mma_bf16(s1[0], s1[1], s1[2], s1[3], al[0], al[1], al[2], al[3], bh2, bh3);
            }
        }

        // ---- online softmax (exp2 domain). slot0: regs 0,1; slot1: regs 2,3 ----
        float mx0 = -1e30f, mx1 = -1e30f;
#pragma unroll
        for (int nt = 0; nt < 16; nt++) {
            sacc[nt][0] *= scale2; sacc[nt][1] *= scale2;
            sacc[nt][2] *= scale2; sacc[nt][3] *= scale2;
            mx0 = fmaxf(mx0, fmaxf(sacc[nt][0], sacc[nt][1]));
            mx1 = fmaxf(mx1, fmaxf(sacc[nt][2], sacc[nt][3]));
        }
        mx0 = fmaxf(mx0, __shfl_xor_sync(0xffffffffu, mx0, 1));
        mx0 = fmaxf(mx0, __shfl_xor_sync(0xffffffffu, mx0, 2));
        mx1 = fmaxf(mx1, __shfl_xor_sync(0xffffffffu, mx1, 1));
        mx1 = fmaxf(mx1, __shfl_xor_sync(0xffffffffu, mx1, 2));
        const float mn0 = fmaxf(m0, mx0), mn1 = fmaxf(m1, mx1);
        const float c0 = ex2f(m0 - mn0), c1 = ex2f(m1 - mn1);
        m0 = mn0; m1 = mn1;
        float sum0 = 0.f, sum1 = 0.f;
#pragma unroll
        for (int nt = 0; nt < 16; nt++) {
            sacc[nt][0] = ex2f(sacc[nt][0] - mn0);
            sacc[nt][1] = ex2f(sacc[nt][1] - mn0);
            sacc[nt][2] = ex2f(sacc[nt][2] - mn1);
            sacc[nt][3] = ex2f(sacc[nt][3] - mn1);
            sum0 += sacc[nt][0] + sacc[nt][1];
            sum1 += sacc[nt][2] + sacc[nt][3];
            oacc[nt][0] *= c0; oacc[nt][1] *= c0;
            oacc[nt][2] *= c1; oacc[nt][3] *= c1;
        }
        sum0 += __shfl_xor_sync(0xffffffffu, sum0, 1);
        sum0 += __shfl_xor_sync(0xffffffffu, sum0, 2);
        sum1 += __shfl_xor_sync(0xffffffffu, sum1, 1);
        sum1 += __shfl_xor_sync(0xffffffffu, sum1, 2);
        l0 = l0 * c0 + sum0;
        l1 = l1 * c1 + sum1;

        // ---- O += P V (3-way split; P split in registers) ----
#pragma unroll
        for (int j = 0; j < 8; j++) {
            const float* p0 = sacc[2 * j];
            const float* p1 = sacc[2 * j + 1];
            uint32_t aph[4], apl[4];
            aph[0] = packbf(p0[0], p0[1]);
            aph[1] = packbf(p0[2], p0[3]);
            aph[2] = packbf(p1[0], p1[1]);
            aph[3] = packbf(p1[2], p1[3]);
#pragma unroll
            for (int q = 0; q < 4; q++) {
                const float* pp = (q < 2) ? p0 : p1;
                const int o = (q & 1) * 2;
                float2 f = __bfloat1622float2(*(__nv_bfloat162*)&aph[q]);
                apl[q] = packbf(pp[o] - f.x, pp[o + 1] - f.y);
            }
#pragma unroll
            for (int np = 0; np < 8; np++) {
                const uint32_t bo = boff_base + np * 16 * FS_STRIDE + j * 32;
                uint32_t bh0, bh1, bh2, bh3, bl0, bl1, bl2, bl3;
                ldmx4(bh0, bh1, bh2, bh3, sb + FVHI + bo);
                ldmx4(bl0, bl1, bl2, bl3, sb + FVLO + bo);
                float* o0 = oacc[np * 2];
                float* o1 = oacc[np * 2 + 1];
                mma_bf16(o0[0], o0[1], o0[2], o0[3], aph[0], aph[1], aph[2], aph[3], bh0, bh1);
                mma_bf16(o1[0], o1[1], o1[2], o1[3], aph[0], aph[1], aph[2], aph[3], bh2, bh3);
                mma_bf16(o0[0], o0[1], o0[2], o0[3], aph[0], aph[1], aph[2], aph[3], bl0, bl1);
                mma_bf16(o1[0], o1[1], o1[2], o1[3], aph[0], aph[1], aph[2], aph[3], bl2, bl3);
                mma_bf16(o0[0], o0[1], o0[2], o0[3], apl[0], apl[1], apl[2], apl[3], bh0, bh1);
                mma_bf16(o1[0], o1[1], o1[2], o1[3], apl[0], apl[1], apl[2], apl[3], bh2, bh3);
            }
        }

        // ---- load next K/VT tile (single buffer) ----
        if (kt + 1 < S_ / 128) {
            __syncthreads();
            const int kv0 = (kt + 1) * 128;
            load_tile(FKHI, khp + (size_t)kv0 * KVN_, KVN_);
            load_tile(FKLO, klp + (size_t)kv0 * KVN_, KVN_);
            load_tile(FVHI, vhp + kv0, S_);
            load_tile(FVLO, vlp + kv0, S_);
            cp_commit();
            cp_wait<0>();
            __syncthreads();
        }
    }

    // ---- epilogue ----
    const float i0 = 1.f / l0, i1 = 1.f / l1;
    const int r0g = q0 + w * 16 + (lane >> 2);
    const int col0 = h * 128 + ((lane & 3) << 1);
#pragma unroll
    for (int nt = 0; nt < 16; nt++) {
        const int col = col0 + nt * 8;
        *(float2*)&O[(size_t)(b * S_ + r0g) * E_ + col] =
            make_float2(oacc[nt][0] * i0, oacc[nt][1] * i0);
        *(float2*)&O[(size_t)(b * S_ + r0g + 8) * E_ + col] =
            make_float2(oacc[nt][2] * i1, oacc[nt][3] * i1);
    }
}

// ================================ launch =====================================
extern "C" void kernel_launch(void* const* d_in, const int* in_sizes, int n_in,
                              void* d_out, int out_size) {
    const float* x   = (const float*)d_in[0];
    const float* Wq  = (const float*)d_in[1];
    const float* bq  = (const float*)d_in[2];
    const float* Wkv = (const float*)d_in[3];
    const float* bkv = (const float*)d_in[4];
    const float* Wo  = (const float*)d_in[5];
    float* out = (float*)d_out;

    float *qb, *kvb, *ob;
    cudaGetSymbolAddress((void**)&qb,  g_qproj);
    cudaGetSymbolAddress((void**)&kvb, g_kvproj);
    cudaGetSymbolAddress((void**)&ob,  g_attno);
    unsigned short *xhi, *xlo, *wqhi, *wqlo, *wkvhi, *wkvlo, *wohi, *wolo, *aohi, *aolo;
    unsigned short *qhi, *qlo, *kvphi, *kvplo, *vthi, *vtlo;
    cudaGetSymbolAddress((void**)&xhi,  g_xhi);
    cudaGetSymbolAddress((void**)&xlo,  g_xlo);
    cudaGetSymbolAddress((void**)&wqhi, g_wqhi);
    cudaGetSymbolAddress((void**)&wqlo, g_wqlo);
    cudaGetSymbolAddress((void**)&wkvhi, g_wkvhi);
    cudaGetSymbolAddress((void**)&wkvlo, g_wkvlo);
    cudaGetSymbolAddress((void**)&wohi, g_wohi);
    cudaGetSymbolAddress((void**)&wolo, g_wolo);
    cudaGetSymbolAddress((void**)&aohi, g_aohi);
    cudaGetSymbolAddress((void**)&aolo, g_aolo);
    cudaGetSymbolAddress((void**)&qhi,  g_qhi);
    cudaGetSymbolAddress((void**)&qlo,  g_qlo);
    cudaGetSymbolAddress((void**)&kvphi, g_kvphi);
    cudaGetSymbolAddress((void**)&kvplo, g_kvplo);
    cudaGetSymbolAddress((void**)&vthi, g_vthi);
    cudaGetSymbolAddress((void**)&vtlo, g_vtlo);

    // fp32 -> bf16 hi/lo splits of inputs/weights
    {
        int n4;
        n4 = M_ * E_ / 4;   split_bf16<<<(n4 + 255) / 256, 256>>>(x,   xhi,  xlo,  n4);
        n4 = E_ * E_ / 4;   split_bf16<<<(n4 + 255) / 256, 256>>>(Wq,  wqhi, wqlo, n4);
        n4 = KVN_ * E_ / 4; split_bf16<<<(n4 + 255) / 256, 256>>>(Wkv, wkvhi, wkvlo, n4);
        n4 = E_ * E_ / 4;   split_bf16<<<(n4 + 255) / 256, 256>>>(Wo,  wohi, wolo, n4);
    }

    // Q / KV projections
    gemm_hmma_x3<<<dim3(E_ / 128, M_ / 128), 256>>>(
        xhi, xlo, wqhi, wqlo, bq, qb, M_, E_, E_);
    gemm_hmma_x3<<<dim3(KVN_ / 128, M_ / 128), 256>>>(
        xhi, xlo, wkvhi, wkvlo, bkv, kvb, M_, KVN_, E_);

    // RoPE on Q and K
    {
        int totq = M_ * H_ * 64;
        rope_kernel<<<(totq + 255) / 256, 256>>>(qb, H_, E_);
        int totk = M_ * KVH_ * 64;
        rope_kernel<<<(totk + 255) / 256, 256>>>(kvb, KVH_, KVN_);
    }

    // split Q/K for flash; transpose+split V
    {
        int n4 = M_ * E_ / 4;
        split_bf16<<<(n4 + 255) / 256, 256>>>(qb, qhi, qlo, n4);
        n4 = M_ * KVN_ / 4;
        split_bf16<<<(n4 + 255) / 256, 256>>>(kvb, kvphi, kvplo, n4);
        vtrans_split<<<dim3(S_ / 32, D_ / 32, B_ * KVH_), 256>>>(kvb, vthi, vtlo);
    }

    // HMMA flash attention
    {
        cudaFuncSetAttribute(flash_hmma,
                             cudaFuncAttributeMaxDynamicSharedMemorySize, FS_SMEM);
        flash_hmma<<<dim3(S_ / 128, B_ * H_), 256, FS_SMEM>>>(
            qhi, qlo, kvphi, kvplo, vthi, vtlo, ob);
    }

    // split attention output, O projection
    {
        int n4 = M_ * E_ / 4;
        split_bf16<<<(n4 + 255) / 256, 256>>>(ob, aohi, aolo, n4);
    }
    gemm_hmma_x3<<<dim3(E_ / 128, M_ / 128), 256>>>(
        aohi, aolo, wohi, wolo, nullptr, out, M_, E_, E_);
}

// round 7
// speedup vs baseline: 2.8071x; 1.0017x over previous
#include <cuda_runtime.h>
#include <cuda_bf16.h>
#include <math.h>
#include <stdint.h>

// Problem constants
#define B_   2
#define S_   2048
#define E_   2048
#define H_   16
#define KVH_ 4
#define D_   128
#define M_   (B_ * S_)        // 4096 rows
#define KVN_ (2 * KVH_ * D_)  // 1024

// ---------------- scratch (device globals; no allocs allowed) ----------------
__device__ float g_qproj[(size_t)M_ * E_];
__device__ float g_kvproj[(size_t)M_ * KVN_];

__device__ unsigned short g_xhi[(size_t)M_ * E_];
__device__ unsigned short g_xlo[(size_t)M_ * E_];
__device__ unsigned short g_wqhi[(size_t)E_ * E_];
__device__ unsigned short g_wqlo[(size_t)E_ * E_];
__device__ unsigned short g_wkvhi[(size_t)KVN_ * E_];
__device__ unsigned short g_wkvlo[(size_t)KVN_ * E_];
__device__ unsigned short g_wohi[(size_t)E_ * E_];
__device__ unsigned short g_wolo[(size_t)E_ * E_];
__device__ unsigned short g_aohi[(size_t)M_ * E_];
__device__ unsigned short g_aolo[(size_t)M_ * E_];
// flash operands (bf16 hi/lo)
__device__ unsigned short g_qhi[(size_t)M_ * E_];
__device__ unsigned short g_qlo[(size_t)M_ * E_];
__device__ unsigned short g_kvphi[(size_t)M_ * KVN_];
__device__ unsigned short g_kvplo[(size_t)M_ * KVN_];
__device__ unsigned short g_vthi[(size_t)B_ * KVH_ * D_ * S_];
__device__ unsigned short g_vtlo[(size_t)B_ * KVH_ * D_ * S_];

// ============================ PTX helpers ====================================
__device__ __forceinline__ uint32_t smem_u32(const void* p) {
    uint32_t a;
    asm("{ .reg .u64 t; cvta.to.shared.u64 t, %1; cvt.u32.u64 %0, t; }"
        : "=r"(a) : "l"(p));
    return a;
}
__device__ __forceinline__ void cp_async16(uint32_t dst, const void* src) {
    asm volatile("cp.async.cg.shared.global [%0], [%1], 16;"
                 :: "r"(dst), "l"(src) : "memory");
}
__device__ __forceinline__ void cp_commit() {
    asm volatile("cp.async.commit_group;" ::: "memory");
}
template <int N>
__device__ __forceinline__ void cp_wait() {
    asm volatile("cp.async.wait_group %0;" :: "n"(N) : "memory");
}
__device__ __forceinline__ void ldmx4(uint32_t& r0, uint32_t& r1, uint32_t& r2,
                                      uint32_t& r3, uint32_t addr) {
    asm volatile("ldmatrix.sync.aligned.m8n8.x4.shared.b16 {%0,%1,%2,%3}, [%4];"
                 : "=r"(r0), "=r"(r1), "=r"(r2), "=r"(r3) : "r"(addr));
}
__device__ __forceinline__ void mma_bf16(float& d0, float& d1, float& d2, float& d3,
                                         uint32_t a0, uint32_t a1, uint32_t a2,
                                         uint32_t a3, uint32_t b0, uint32_t b1) {
    asm volatile(
        "mma.sync.aligned.m16n8k16.row.col.f32.bf16.bf16.f32 "
        "{%0,%1,%2,%3}, {%4,%5,%6,%7}, {%8,%9}, {%0,%1,%2,%3};"
        : "+f"(d0), "+f"(d1), "+f"(d2), "+f"(d3)
        : "r"(a0), "r"(a1), "r"(a2), "r"(a3), "r"(b0), "r"(b1));
}
__device__ __forceinline__ float ex2f(float x) {
    float y;
    asm("ex2.approx.ftz.f32 %0, %1;" : "=f"(y) : "f"(x));
    return y;
}
__device__ __forceinline__ uint32_t packbf(float a, float b) {
    __nv_bfloat162 t = __floats2bfloat162_rn(a, b);
    return *(uint32_t*)&t;
}

// ====================== fp32 -> bf16 hi/lo split =============================
__device__ __forceinline__ void split1(float x, unsigned short& h, unsigned short& l) {
    __nv_bfloat16 bh = __float2bfloat16_rn(x);
    float r = x - __bfloat162float(bh);
    __nv_bfloat16 bl = __float2bfloat16_rn(r);
    h = __bfloat16_as_ushort(bh);
    l = __bfloat16_as_ushort(bl);
}
__global__ void __launch_bounds__(256) split_bf16(const float* __restrict__ in,
                                                  unsigned short* __restrict__ hi,
                                                  unsigned short* __restrict__ lo,
                                                  int n4) {
    int i = blockIdx.x * blockDim.x + threadIdx.x;
    if (i >= n4) return;
    float4 v = ((const float4*)in)[i];
    ushort4 h, l;
    split1(v.x, h.x, l.x);
    split1(v.y, h.y, l.y);
    split1(v.z, h.z, l.z);
    split1(v.w, h.w, l.w);
    ((ushort4*)hi)[i] = h;
    ((ushort4*)lo)[i] = l;
}

// ==================== RoPE fused with bf16 hi/lo split =======================
__global__ void __launch_bounds__(256)
rope_split(const float* __restrict__ t, unsigned short* __restrict__ hi,
           unsigned short* __restrict__ lo, int nHeads, int rowStride) {
    int idx = blockIdx.x * blockDim.x + threadIdx.x;
    int total = M_ * nHeads * 64;
    if (idx >= total) return;
    int i = idx & 63;
    int h = (idx >> 6) % nHeads;
    int m = idx / (64 * nHeads);
    int s = m & (S_ - 1);
    float inv = powf(10000.0f, -(float)i * (1.0f / 64.0f));
    float fr = (float)s * inv;
    float sn, cs;
    sincosf(fr, &sn, &cs);
    const float* p = t + (size_t)m * rowStride + h * 128 + i;
    float v1 = p[0], v2 = p[64];
    float o1 = v1 * cs - v2 * sn;
    float o2 = v2 * cs + v1 * sn;
    size_t o = (size_t)m * rowStride + h * 128 + i;
    unsigned short h1, l1, h2, l2;
    split1(o1, h1, l1);
    split1(o2, h2, l2);
    hi[o] = h1; lo[o] = l1;
    hi[o + 64] = h2; lo[o + 64] = l2;
}

// ============ V transpose + split: kvproj V-part -> VT[d, s] bf16 ============
__global__ void __launch_bounds__(256) vtrans_split(const float* __restrict__ kv,
                                                    unsigned short* __restrict__ vthi,
                                                    unsigned short* __restrict__ vtlo) {
    __shared__ float t[32][33];
    const int s0 = blockIdx.x * 32, d0 = blockIdx.y * 32;
    const int bk = blockIdx.z;
    const int b = bk >> 2, kvh = bk & 3;
    const int tx = threadIdx.x & 31, ty = threadIdx.x >> 5;
#pragma unroll
    for (int i = 0; i < 4; i++) {
        int s = s0 + ty + i * 8;
        t[ty + i * 8][tx] =
            kv[(size_t)(b * S_ + s) * KVN_ + KVH_ * D_ + kvh * 128 + d0 + tx];
    }
    __syncthreads();
#pragma unroll
    for (int i = 0; i < 4; i++) {
        int d = d0 + ty + i * 8;
        float v = t[tx][ty + i * 8];
        unsigned short hi, lo;
        split1(v, hi, lo);
        size_t o = ((size_t)bk * 128 + d) * S_ + s0 + tx;
        vthi[o] = hi;
        vtlo[o] = lo;
    }
}

// =============== HMMA GEMM: C = A@W^T (+bias), 3x bf16 split =================
#define GS_STRIDE 80
#define GS_BUF    (128 * GS_STRIDE)

__global__ void __launch_bounds__(256)
gemm_hmma_x3(const unsigned short* __restrict__ Ahi, const unsigned short* __restrict__ Alo,
             const unsigned short* __restrict__ Bhi, const unsigned short* __restrict__ Blo,
             const float* __restrict__ bias, float* __restrict__ C,
             int M, int N, int K) {
    __shared__ __align__(16) unsigned char smem[4 * GS_BUF];
    const uint32_t sb = smem_u32(smem);
    const int tid = threadIdx.x;
    const int wid = tid >> 5, lane = tid & 31;
    const int wm = wid & 3;
    const int wn = wid >> 2;
    const int m0 = blockIdx.y * 128, n0 = blockIdx.x * 128;

    const int NCH = 3 * (K >> 5);
    const int segC = K >> 5;

    float acc[2][8][4];
#pragma unroll
    for (int mt = 0; mt < 2; mt++)
#pragma unroll
        for (int nt = 0; nt < 8; nt++)
#pragma unroll
            for (int i = 0; i < 4; i++) acc[mt][nt][i] = 0.f;

    auto issue = [&](int c, int buf) {
        const int seg = c / segC;
        const int kk = (c % segC) << 5;
        const unsigned short* Ap = (seg == 2) ? Alo : Ahi;
        const unsigned short* Bp = (seg == 1) ? Blo : Bhi;
#pragma unroll
        for (int h = 0; h < 2; h++) {
            const int u = tid + h * 256;
            const int row = u >> 2;
            const int kb = (u & 3) << 3;
            cp_async16(sb + buf * GS_BUF + row * GS_STRIDE + (kb << 1),
                       Ap + (size_t)(m0 + row) * K + kk + kb);
            cp_async16(sb + 2 * GS_BUF + buf * GS_BUF + row * GS_STRIDE + (kb << 1),
                       Bp + (size_t)(n0 + row) * K + kk + kb);
        }
        cp_commit();
    };

    issue(0, 0);
    int buf = 0;
    for (int c = 0; c < NCH; c++) {
        if (c + 1 < NCH) { issue(c + 1, buf ^ 1); cp_wait<1>(); }
        else             { cp_wait<0>(); }
        __syncthreads();

        const uint32_t abase = sb + buf * GS_BUF;
        const uint32_t bbase = sb + 2 * GS_BUF + buf * GS_BUF;
#pragma unroll
        for (int ks = 0; ks < 2; ks++) {
            const int kbyte = ks * 32;
            uint32_t a[2][4];
#pragma unroll
            for (int mt = 0; mt < 2; mt++) {
                const int row = wm * 32 + mt * 16 + (lane & 15);
                ldmx4(a[mt][0], a[mt][1], a[mt][2], a[mt][3],
                      abase + row * GS_STRIDE + kbyte + ((lane >> 4) << 4));
            }
            uint32_t b[8][2];
#pragma unroll
            for (int np = 0; np < 4; np++) {
                const int row = wn * 64 + np * 16 + (((lane >> 4) & 1) << 3) + (lane & 7);
                uint32_t r0, r1, r2, r3;
                ldmx4(r0, r1, r2, r3,
                      bbase + row * GS_STRIDE + kbyte + (((lane >> 3) & 1) << 4));
                b[np * 2][0] = r0; b[np * 2][1] = r1;
                b[np * 2 + 1][0] = r2; b[np * 2 + 1][1] = r3;
            }
#pragma unroll
            for (int mt = 0; mt < 2; mt++)
#pragma unroll
                for (int nt = 0; nt < 8; nt++)
                    mma_bf16(acc[mt][nt][0], acc[mt][nt][1],
                             acc[mt][nt][2], acc[mt][nt][3],
                             a[mt][0], a[mt][1], a[mt][2], a[mt][3],
                             b[nt][0], b[nt][1]);
        }
        __syncthreads();
        buf ^= 1;
    }

    const int mrow = m0 + wm * 32 + (lane >> 2);
    const int ncol0 = n0 + wn * 64 + ((lane & 3) << 1);
#pragma unroll
    for (int mt = 0; mt < 2; mt++) {
#pragma unroll
        for (int nt = 0; nt < 8; nt++) {
            const int n = ncol0 + nt * 8;
            float b0 = bias ? bias[n] : 0.f;
            float b1 = bias ? bias[n + 1] : 0.f;
            float2 v0 = make_float2(acc[mt][nt][0] + b0, acc[mt][nt][1] + b1);
            float2 v1 = make_float2(acc[mt][nt][2] + b0, acc[mt][nt][3] + b1);
            *(float2*)&C[(size_t)(mrow + mt * 16) * N + n] = v0;
            *(float2*)&C[(size_t)(mrow + mt * 16 + 8) * N + n] = v1;
        }
    }
}

// ===================== HMMA flash attention (3x bf16 split) ==================
// CTA: 128 q rows, 8 warps. KV tile BN=64, double-buffered stages.
// Q persists in smem; K row-major [s,d]; V via VT [d,s].
#define F2_QHI   0
#define F2_QLO   34816
#define F2_Q     69632
#define F2_STAGE 71680            // KHI 0 | KLO 17408 | VHI 34816 | VLO 53248
#define F2_SMEM  (F2_Q + 2 * F2_STAGE)   // 212992 B

__global__ void __launch_bounds__(256)
flash_hmma(const unsigned short* __restrict__ qhi, const unsigned short* __restrict__ qlo,
           const unsigned short* __restrict__ khi, const unsigned short* __restrict__ klo,
           const unsigned short* __restrict__ vthi, const unsigned short* __restrict__ vtlo,
           unsigned short* __restrict__ Ohi, unsigned short* __restrict__ Olo) {
    extern __shared__ __align__(16) unsigned char fsm2[];
    const uint32_t sb = smem_u32(fsm2);
    const int tid = threadIdx.x;
    const int w = tid >> 5, lane = tid & 31;
    const int bh = blockIdx.y;
    const int b = bh >> 4, h = bh & 15;
    const int kvh = h >> 2;
    const int q0 = blockIdx.x * 128;
    const float scale2 = 0.127518795f;    // (1/sqrt(128)) * log2(e)

    const unsigned short* qhp = qhi + (size_t)(b * S_ + q0) * E_ + h * 128;
    const unsigned short* qlp = qlo + (size_t)(b * S_ + q0) * E_ + h * 128;
    const unsigned short* khp = khi + (size_t)b * S_ * KVN_ + kvh * 128;
    const unsigned short* klp = klo + (size_t)b * S_ * KVN_ + kvh * 128;
    const unsigned short* vhp = vthi + ((size_t)(b * KVH_ + kvh) * 128) * S_;
    const unsigned short* vlp = vtlo + ((size_t)(b * KVH_ + kvh) * 128) * S_;

    auto load_q = [&](uint32_t dst, const unsigned short* src) {
#pragma unroll
        for (int it = 0; it < 8; it++) {
            int u = tid + it * 256;          // 128 rows x 256B
            int row = u >> 4;
            int cb = (u & 15) << 4;
            cp_async16(sb + dst + row * 272 + cb,
                       (const char*)src + (size_t)row * E_ * 2 + cb);
        }
    };
    auto load_k64 = [&](uint32_t dst, const unsigned short* src) {
#pragma unroll
        for (int it = 0; it < 4; it++) {
            int u = tid + it * 256;          // 64 rows x 256B
            int row = u >> 4;
            int cb = (u & 15) << 4;
            cp_async16(sb + dst + row * 272 + cb,
                       (const char*)src + (size_t)row * KVN_ * 2 + cb);
        }
    };
    auto load_v64 = [&](uint32_t dst, const unsigned short* src) {
#pragma unroll
        for (int it = 0; it < 4; it++) {
            int u = tid + it * 256;          // 128 rows x 128B
            int row = u >> 3;
            int cb = (u & 7) << 4;
            cp_async16(sb + dst + row * 144 + cb,
                       (const char*)src + (size_t)row * S_ * 2 + cb);
        }
    };
    auto issue_stage = [&](int stg, int kv0) {
        const uint32_t base = F2_Q + stg * F2_STAGE;
        load_k64(base,         khp + (size_t)kv0 * KVN_);
        load_k64(base + 17408, klp + (size_t)kv0 * KVN_);
        load_v64(base + 34816, vhp + kv0);
        load_v64(base + 53248, vlp + kv0);
        cp_commit();
    };

    // initial: Q + stage 0
    load_q(F2_QHI, qhp);
    load_q(F2_QLO, qlp);
    issue_stage(0, 0);
    cp_wait<0>();
    __syncthreads();

    float oacc[16][4];
#pragma unroll
    for (int nt = 0; nt < 16; nt++)
#pragma unroll
        for (int i = 0; i < 4; i++) oacc[nt][i] = 0.f;
    float m0 = -1e30f, m1 = -1e30f, l0 = 0.f, l1 = 0.f;

    const int arow = w * 16 + (lane & 15);
    const uint32_t aoff_base = arow * 272 + ((lane >> 4) << 4);
    const int brow = (((lane >> 4) & 1) << 3) + (lane & 7);
    const uint32_t bko = brow * 272 + (((lane >> 3) & 1) << 4);
    const uint32_t bvo = brow * 144 + (((lane >> 3) & 1) << 4);

    int buf = 0;
    for (int kt = 0; kt < S_ / 64; kt++) {
        if (kt + 1 < S_ / 64) issue_stage(buf ^ 1, (kt + 1) * 64);
        const uint32_t sk = sb + F2_Q + buf * F2_STAGE;

        float sacc[8][4];
#pragma unroll
        for (int nt = 0; nt < 8; nt++)
#pragma unroll
            for (int i = 0; i < 4; i++) sacc[nt][i] = 0.f;

        // ---- S = Q K^T (3-way split) ----
#pragma unroll
        for (int ks = 0; ks < 8; ks++) {
            uint32_t ah[4], al[4];
            ldmx4(ah[0], ah[1], ah[2], ah[3], sb + F2_QHI + aoff_base + ks * 32);
            ldmx4(al[0], al[1], al[2], al[3], sb + F2_QLO + aoff_base + ks * 32);
#pragma unroll
            for (int np = 0; np < 4; np++) {
                const uint32_t bo = bko + np * 16 * 272 + ks * 32;
                uint32_t bh0, bh1, bh2, bh3, bl0, bl1, bl2, bl3;
                ldmx4(bh0, bh1, bh2, bh3, sk + bo);
                ldmx4(bl0, bl1, bl2, bl3, sk + 17408 + bo);
                float* s0 = sacc[np * 2];
                float* s1 = sacc[np * 2 + 1];
                mma_bf16(s0[0], s0[1], s0[2], s0[3], ah[0], ah[1], ah[2], ah[3], bh0, bh1);
                mma_bf16(s1[0], s1[1], s1[2], s1[3], ah[0], ah[1], ah[2], ah[3], bh2, bh3);
                mma_bf16(s0[0], s0[1], s0[2], s0[3], ah[0], ah[1], ah[2], ah[3], bl0, bl1);
                mma_bf16(s1[0], s1[1], s1[2], s1[3], ah[0], ah[1], ah[2], ah[3], bl2, bl3);
                mma_bf16(s0[0], s0[1], s0[2], s0[3], al[0], al[1], al[2], al[3], bh0, bh1);
                mma_bf16(s1[0], s1[1], s1[2], s1[3], al[0], al[1], al[2], al[3], bh2, bh3);
            }
        }

        // ---- online softmax (exp2 domain) ----
        float mx0 = -1e30f, mx1 = -1e30f;
#pragma unroll
        for (int nt = 0; nt < 8; nt++) {
            sacc[nt][0] *= scale2; sacc[nt][1] *= scale2;
            sacc[nt][2] *= scale2; sacc[nt][3] *= scale2;
            mx0 = fmaxf(mx0, fmaxf(sacc[nt][0], sacc[nt][1]));
            mx1 = fmaxf(mx1, fmaxf(sacc[nt][2], sacc[nt][3]));
        }
        mx0 = fmaxf(mx0, __shfl_xor_sync(0xffffffffu, mx0, 1));
        mx0 = fmaxf(mx0, __shfl_xor_sync(0xffffffffu, mx0, 2));
        mx1 = fmaxf(mx1, __shfl_xor_sync(0xffffffffu, mx1, 1));
        mx1 = fmaxf(mx1, __shfl_xor_sync(0xffffffffu, mx1, 2));
        const float mn0 = fmaxf(m0, mx0), mn1 = fmaxf(m1, mx1);
        const float c0 = ex2f(m0 - mn0), c1 = ex2f(m1 - mn1);
        m0 = mn0; m1 = mn1;
        float sum0 = 0.f, sum1 = 0.f;
#pragma unroll
        for (int nt = 0; nt < 8; nt++) {
            sacc[nt][0] = ex2f(sacc[nt][0] - mn0);
            sacc[nt][1] = ex2f(sacc[nt][1] - mn0);
            sacc[nt][2] = ex2f(sacc[nt][2] - mn1);
            sacc[nt][3] = ex2f(sacc[nt][3] - mn1);
            sum0 += sacc[nt][0] + sacc[nt][1];
            sum1 += sacc[nt][2] + sacc[nt][3];
        }
#pragma unroll
        for (int nt = 0; nt < 16; nt++) {
            oacc[nt][0] *= c0; oacc[nt][1] *= c0;
            oacc[nt][2] *= c1; oacc[nt][3] *= c1;
        }
        sum0 += __shfl_xor_sync(0xffffffffu, sum0, 1);
        sum0 += __shfl_xor_sync(0xffffffffu, sum0, 2);
        sum1 += __shfl_xor_sync(0xffffffffu, sum1, 1);
        sum1 += __shfl_xor_sync(0xffffffffu, sum1, 2);
        l0 = l0 * c0 + sum0;
        l1 = l1 * c1 + sum1;

        // ---- O += P V (3-way split; P split in registers) ----
#pragma unroll
        for (int j = 0; j < 4; j++) {
            const float* p0 = sacc[2 * j];
            const float* p1 = sacc[2 * j + 1];
            uint32_t aph[4], apl[4];
            aph[0] = packbf(p0[0], p0[1]);
            aph[1] = packbf(p0[2], p0[3]);
            aph[2] = packbf(p1[0], p1[1]);
            aph[3] = packbf(p1[2], p1[3]);
#pragma unroll
            for (int q = 0; q < 4; q++) {
                const float* pp = (q < 2) ? p0 : p1;
                const int o = (q & 1) * 2;
                float2 f = __bfloat1622float2(*(__nv_bfloat162*)&aph[q]);
                apl[q] = packbf(pp[o] - f.x, pp[o + 1] - f.y);
            }
#pragma unroll
            for (int np = 0; np < 8; np++) {
                const uint32_t bo = bvo + np * 16 * 144 + j * 32;
                uint32_t bh0, bh1, bh2, bh3, bl0, bl1, bl2, bl3;
                ldmx4(bh0, bh1, bh2, bh3, sk + 34816 + bo);
                ldmx4(bl0, bl1, bl2, bl3, sk + 53248 + bo);
                float* o0 = oacc[np * 2];
                float* o1 = oacc[np * 2 + 1];
                mma_bf16(o0[0], o0[1], o0[2], o0[3], aph[0], aph[1], aph[2], aph[3], bh0, bh1);
                mma_bf16(o1[0], o1[1], o1[2], o1[3], aph[0], aph[1], aph[2], aph[3], bh2, bh3);
                mma_bf16(o0[0], o0[1], o0[2], o0[3], aph[0], aph[1], aph[2], aph[3], bl0, bl1);
                mma_bf16(o1[0], o1[1], o1[2], o1[3], aph[0], aph[1], aph[2], aph[3], bl2, bl3);
                mma_bf16(o0[0], o0[1], o0[2], o0[3], apl[0], apl[1], apl[2], apl[3], bh0, bh1);
                mma_bf16(o1[0], o1[1], o1[2], o1[3], apl[0], apl[1], apl[2], apl[3], bh2, bh3);
            }
        }

        if (kt + 1 < S_ / 64) cp_wait<0>();
        __syncthreads();
        buf ^= 1;
    }

    // ---- epilogue: write bf16 hi/lo directly ----
    const float i0 = 1.f / l0, i1 = 1.f / l1;
    const int r0g = q0 + w * 16 + (lane >> 2);
    const int col0 = h * 128 + ((lane & 3) << 1);
#pragma unroll
    for (int nt = 0; nt < 16; nt++) {
        const int col = col0 + nt * 8;
        const size_t idx0 = (size_t)(b * S_ + r0g) * E_ + col;
        const size_t idx1 = (size_t)(b * S_ + r0g + 8) * E_ + col;
        float f0 = oacc[nt][0] * i0, f1 = oacc[nt][1] * i0;
        float f2 = oacc[nt][2] * i1, f3 = oacc[nt][3] * i1;
        unsigned short ha, la, hbv, lb;
        split1(f0, ha, la); split1(f1, hbv, lb);
        *(ushort2*)&Ohi[idx0] = make_ushort2(ha, hbv);
        *(ushort2*)&Olo[idx0] = make_ushort2(la, lb);
        split1(f2, ha, la); split1(f3, hbv, lb);
        *(ushort2*)&Ohi[idx1] = make_ushort2(ha, hbv);
        *(ushort2*)&Olo[idx1] = make_ushort2(la, lb);
    }
}

// ================================ launch =====================================
extern "C" void kernel_launch(void* const* d_in, const int* in_sizes, int n_in,
                              void* d_out, int out_size) {
    const float* x   = (const float*)d_in[0];
    const float* Wq  = (const float*)d_in[1];
    const float* bq  = (const float*)d_in[2];
    const float* Wkv = (const float*)d_in[3];
    const float* bkv = (const float*)d_in[4];
    const float* Wo  = (const float*)d_in[5];
    float* out = (float*)d_out;

    float *qb, *kvb;
    cudaGetSymbolAddress((void**)&qb,  g_qproj);
    cudaGetSymbolAddress((void**)&kvb, g_kvproj);
    unsigned short *xhi, *xlo, *wqhi, *wqlo, *wkvhi, *wkvlo, *wohi, *wolo, *aohi, *aolo;
    unsigned short *qhi, *qlo, *kvphi, *kvplo, *vthi, *vtlo;
    cudaGetSymbolAddress((void**)&xhi,  g_xhi);
    cudaGetSymbolAddress((void**)&xlo,  g_xlo);
    cudaGetSymbolAddress((void**)&wqhi, g_wqhi);
    cudaGetSymbolAddress((void**)&wqlo, g_wqlo);
    cudaGetSymbolAddress((void**)&wkvhi, g_wkvhi);
    cudaGetSymbolAddress((void**)&wkvlo, g_wkvlo);
    cudaGetSymbolAddress((void**)&wohi, g_wohi);
    cudaGetSymbolAddress((void**)&wolo, g_wolo);
    cudaGetSymbolAddress((void**)&aohi, g_aohi);
    cudaGetSymbolAddress((void**)&aolo, g_aolo);
    cudaGetSymbolAddress((void**)&qhi,  g_qhi);
    cudaGetSymbolAddress((void**)&qlo,  g_qlo);
    cudaGetSymbolAddress((void**)&kvphi, g_kvphi);
    cudaGetSymbolAddress((void**)&kvplo, g_kvplo);
    cudaGetSymbolAddress((void**)&vthi, g_vthi);
    cudaGetSymbolAddress((void**)&vtlo, g_vtlo);

    // fp32 -> bf16 hi/lo splits of input + weights
    {
        int n4;
        n4 = M_ * E_ / 4;   split_bf16<<<(n4 + 255) / 256, 256>>>(x,   xhi,  xlo,  n4);
        n4 = E_ * E_ / 4;   split_bf16<<<(n4 + 255) / 256, 256>>>(Wq,  wqhi, wqlo, n4);
        n4 = KVN_ * E_ / 4; split_bf16<<<(n4 + 255) / 256, 256>>>(Wkv, wkvhi, wkvlo, n4);
        n4 = E_ * E_ / 4;   split_bf16<<<(n4 + 255) / 256, 256>>>(Wo,  wohi, wolo, n4);
    }

    // Q / KV projections (fp32 out)
    gemm_hmma_x3<<<dim3(E_ / 128, M_ / 128), 256>>>(
        xhi, xlo, wqhi, wqlo, bq, qb, M_, E_, E_);
    gemm_hmma_x3<<<dim3(KVN_ / 128, M_ / 128), 256>>>(
        xhi, xlo, wkvhi, wkvlo, bkv, kvb, M_, KVN_, E_);

    // RoPE fused with split (Q, K); V transpose+split
    {
        int totq = M_ * H_ * 64;
        rope_split<<<(totq + 255) / 256, 256>>>(qb, qhi, qlo, H_, E_);
        int totk = M_ * KVH_ * 64;
        rope_split<<<(totk + 255) / 256, 256>>>(kvb, kvphi, kvplo, KVH_, KVN_);
        vtrans_split<<<dim3(S_ / 32, D_ / 32, B_ * KVH_), 256>>>(kvb, vthi, vtlo);
    }

    // HMMA flash attention (writes bf16 hi/lo directly)
    {
        cudaFuncSetAttribute(flash_hmma,
                             cudaFuncAttributeMaxDynamicSharedMemorySize, F2_SMEM);
        flash_hmma<<<dim3(S_ / 128, B_ * H_), 256, F2_SMEM>>>(
            qhi, qlo, kvphi, kvplo, vthi, vtlo, aohi, aolo);
    }

    // O projection
    gemm_hmma_x3<<<dim3(E_ / 128, M_ / 128), 256>>>(
        aohi, aolo, wohi, wolo, nullptr, out, M_, E_, E_);
}